// round 16
// baseline (speedup 1.0000x reference)
#include <cuda_runtime.h>
#include <cuda_fp16.h>
#include <math.h>
#include <stdint.h>

// Problem constants
#define BB 2
#define EE 1024
#define HH 16
#define DD 64
#define SS 4096            // 64*64 spatial tokens per batch
#define BNS (BB*SS)        // 8192 total tokens
#define E4 (4*EE)          // 4096 ffn hidden

typedef __half h16;
typedef __half2 h162;

#define M1 (1L<<20)        // 1M elements (EE*EE)

// ---------------- device scratch ----------------
__device__ h16   g_work[(long)BNS*EE];        // fp16 working residual
__device__ h16   g_x   [(long)BNS*EE];        // fp16 staging (q-act / attn out / grn2 out)
__device__ h16   g_w   [12*M1];               // all 6 weights fp16: q|k|v|o|w1|w2
__device__ h16   g_h   [(long)BNS*E4];        // fp16: q|k|v slices, later ffn hidden
__device__ h16   g_o1  [(long)BNS*EE];        // fp16: k-act staging, later o-proj out
__device__ h16   g_o2  [(long)BNS*EE];        // fp16: v-act staging, later ffn2 out
__device__ float g_kv  [BB*HH*DD*DD + BB*HH*DD];  // kv | ksum
__device__ float g_sumsq[BB*EE];
__device__ float g_lnst [4*BNS];              // qmean | qrstd | kmean | krstd

// ================= helpers =================
__device__ __forceinline__ uint32_t smem_u32(const void* p) {
    uint32_t a;
    asm("{ .reg .u64 t; cvta.to.shared.u64 t, %1; cvt.u32.u64 %0, t; }" : "=r"(a) : "l"(p));
    return a;
}
__device__ __forceinline__ void cp16(uint32_t dst, const void* src) {
    asm volatile("cp.async.cg.shared.global [%0], [%1], 16;" :: "r"(dst), "l"(src));
}
__device__ __forceinline__ uint32_t lds32(uint32_t a) {
    uint32_t v;
    asm volatile("ld.shared.u32 %0, [%1];" : "=r"(v) : "r"(a));
    return v;
}
__device__ __forceinline__ void mma16816(float* c, const uint32_t* a, const uint32_t* b) {
    asm volatile(
        "mma.sync.aligned.m16n8k16.row.col.f32.f16.f16.f32 "
        "{%0,%1,%2,%3}, {%4,%5,%6,%7}, {%8,%9}, {%0,%1,%2,%3};"
        : "+f"(c[0]), "+f"(c[1]), "+f"(c[2]), "+f"(c[3])
        : "r"(a[0]), "r"(a[1]), "r"(a[2]), "r"(a[3]), "r"(b[0]), "r"(b[1]));
}
__device__ __forceinline__ float elu1(float y) {
    return (y > 0.f) ? y + 1.f : expf(y);
}

// ====== GEMM: CTA 128x64, KT=64, 8 warps (4M x 2N), warp 32x32,
// ====== register double-buffered fragments (hide LDS latency under MMAs).
#define TPITCH 144
#define TBYTES_A (128*TPITCH)        // 18432
#define TBYTES_B (64*TPITCH)         // 9216
#define STAGEB (TBYTES_A + TBYTES_B) // 27648
#define GSMEM  (2*STAGEB)            // 55296

template<int EPI>
__global__ __launch_bounds__(256, 2) void gemm_hmma(
    const h16* __restrict__ A0, const h16* __restrict__ A1,
    const h16* __restrict__ A2,
    const h16* __restrict__ Wb, long wStride,
    const float* __restrict__ b0, const float* __restrict__ b1,
    const float* __restrict__ b2,
    h16* __restrict__ CHb, long cStride,
    int M, int N, int K)
{
    extern __shared__ char sm[];
    const uint32_t sbase = smem_u32(sm);
    const int tid = threadIdx.x;
    const int lane = tid & 31, wid = tid >> 5;
    const int warp_m = wid >> 1, warp_n = wid & 1;   // 4 x 2
    const int m0 = blockIdx.y * 128, n0 = blockIdx.x * 64;
    const int z = blockIdx.z;
    const int lrow = lane >> 2, lpair = lane & 3;

    const h16* A = (z == 0) ? A0 : (z == 1) ? A1 : A2;
    const float* bias = (z == 0) ? b0 : (z == 1) ? b1 : b2;
    const h16* W = Wb + (long)z * wStride;
    h16* CH = CHb + (long)z * cStride;

    float acc[2][4][4];
    #pragma unroll
    for (int i = 0; i < 2; i++)
        #pragma unroll
        for (int j = 0; j < 4; j++)
            #pragma unroll
            for (int t = 0; t < 4; t++) acc[i][j][t] = 0.f;

    const int nk = K >> 6;

    auto load_stage = [&](int buf, int kc) {
        const long kq = (long)kc * 64;
        uint32_t sb = sbase + buf * STAGEB;
        #pragma unroll
        for (int i = 0; i < 6; i++) {
            int p = tid + i * 256;
            int row = p >> 3, ch = p & 7;
            uint32_t d = sb + row * TPITCH + ch * 16;
            if (row < 128) cp16(d, A + (long)(m0 + row) * K + kq + ch * 8);
            else           cp16(d, W + (long)(n0 + row - 128) * K + kq + ch * 8);
        }
        asm volatile("cp.async.commit_group;");
    };

    load_stage(0, 0);
    if (nk > 1) load_stage(1, 1);

    // per-warp fragment double buffers
    uint32_t aF[2][2][4], bF[2][4][2];

    for (int kc = 0; kc < nk; kc++) {
        const int buf = kc & 1;
        if (kc + 1 < nk) asm volatile("cp.async.wait_group 1;");
        else             asm volatile("cp.async.wait_group 0;");
        __syncthreads();

        const uint32_t aB = sbase + buf * STAGEB;
        const uint32_t bB = aB + TBYTES_A;
        const uint32_t aR = aB + (warp_m * 32 + lrow) * TPITCH;
        const uint32_t bR = bB + (warp_n * 32 + lrow) * TPITCH;

        // preload s=0 fragments into slot 0
        {
            const uint32_t koff = lpair * 4;
            #pragma unroll
            for (int mt = 0; mt < 2; mt++) {
                uint32_t r = aR + mt * 16 * TPITCH;
                aF[0][mt][0] = lds32(r + koff);
                aF[0][mt][1] = lds32(r + 8*TPITCH + koff);
                aF[0][mt][2] = lds32(r + koff + 16);
                aF[0][mt][3] = lds32(r + 8*TPITCH + koff + 16);
            }
            #pragma unroll
            for (int nt = 0; nt < 4; nt++) {
                uint32_t r = bR + nt * 8 * TPITCH;
                bF[0][nt][0] = lds32(r + koff);
                bF[0][nt][1] = lds32(r + koff + 16);
            }
        }

        #pragma unroll
        for (int s = 0; s < 4; s++) {
            const int cur = s & 1, nxt = cur ^ 1;
            if (s < 3) {   // prefetch s+1 fragments while MMAs of s issue
                const uint32_t koff = ((s + 1) * 8 + lpair) * 4;
                #pragma unroll
                for (int mt = 0; mt < 2; mt++) {
                    uint32_t r = aR + mt * 16 * TPITCH;
                    aF[nxt][mt][0] = lds32(r + koff);
                    aF[nxt][mt][1] = lds32(r + 8*TPITCH + koff);
                    aF[nxt][mt][2] = lds32(r + koff + 16);
                    aF[nxt][mt][3] = lds32(r + 8*TPITCH + koff + 16);
                }
                #pragma unroll
                for (int nt = 0; nt < 4; nt++) {
                    uint32_t r = bR + nt * 8 * TPITCH;
                    bF[nxt][nt][0] = lds32(r + koff);
                    bF[nxt][nt][1] = lds32(r + koff + 16);
                }
            }
            #pragma unroll
            for (int mt = 0; mt < 2; mt++)
                #pragma unroll
                for (int nt = 0; nt < 4; nt++)
                    mma16816(acc[mt][nt], aF[cur][mt], bF[cur][nt]);
        }
        __syncthreads();
        if (kc + 2 < nk) load_stage(buf, kc + 2);
    }

    // ---- epilogue ----
    #pragma unroll
    for (int mt = 0; mt < 2; mt++) {
        #pragma unroll
        for (int nt = 0; nt < 4; nt++) {
            long row = m0 + warp_m * 32 + mt * 16 + lrow;
            int col = n0 + warp_n * 32 + nt * 8 + lpair * 2;
            float b0v = bias[col], b1v = bias[col + 1];
            #pragma unroll
            for (int half = 0; half < 2; half++) {
                long r = row + half * 8;
                float v0 = acc[mt][nt][half*2 + 0] + b0v;
                float v1 = acc[mt][nt][half*2 + 1] + b1v;
                if (EPI == 1) {
                    v0 = v0 / (1.f + expf(-v0));
                    v1 = v1 / (1.f + expf(-v1));
                }
                *(h162*)(CH + r * N + col) = __floats2half2_rn(v0, v1);
            }
        }
    }
}

// ================= converters =================
__global__ __launch_bounds__(256) void cvt_weights(
    const float* __restrict__ qw, const float* __restrict__ kw,
    const float* __restrict__ vw, const float* __restrict__ ow,
    const float* __restrict__ w1, const float* __restrict__ w2,
    h16* __restrict__ out)
{
    const long total = 12 * M1;
    const long stride = (long)gridDim.x * blockDim.x * 4;
    for (long i = ((long)blockIdx.x * blockDim.x + threadIdx.x) * 4; i < total;
         i += stride) {
        const float* src;
        long off;
        if (i < 4*M1) {
            int seg = (int)(i >> 20);
            src = (seg == 0) ? qw : (seg == 1) ? kw : (seg == 2) ? vw : ow;
            off = i & (M1 - 1);
        } else if (i < 8*M1) { src = w1; off = i - 4*M1; }
        else                 { src = w2; off = i - 8*M1; }
        float4 v = *(const float4*)(src + off);
        *(h162*)(out + i)     = __floats2half2_rn(v.x, v.y);
        *(h162*)(out + i + 2) = __floats2half2_rn(v.z, v.w);
    }
}

// ---------------- small helpers ----------------
__inline__ __device__ void blockReduce2(float& a, float& b) {
    #pragma unroll
    for (int off = 16; off > 0; off >>= 1) {
        a += __shfl_down_sync(0xffffffffu, a, off);
        b += __shfl_down_sync(0xffffffffu, b, off);
    }
    __shared__ float sa[8], sb[8];
    int w = threadIdx.x >> 5, l = threadIdx.x & 31;
    if (l == 0) { sa[w] = a; sb[w] = b; }
    __syncthreads();
    if (w == 0) {
        a = (l < 8) ? sa[l] : 0.f;
        b = (l < 8) ? sb[l] : 0.f;
        #pragma unroll
        for (int off = 4; off > 0; off >>= 1) {
            a += __shfl_down_sync(0xffu, a, off);
            b += __shfl_down_sync(0xffu, b, off);
        }
        if (l == 0) { sa[0] = a; sb[0] = b; }
    }
    __syncthreads();
    a = sa[0]; b = sb[0];
}

// batched transpose [B,E,S] fp32 -> [B,S,E] fp16; src 0 applies GRN1 (meangx inline).
__global__ __launch_bounds__(256) void trans3(
    const float* __restrict__ qimg, const float* __restrict__ kimg,
    const float* __restrict__ vimg,
    const float* __restrict__ sumsq,
    const float* __restrict__ gamma, const float* __restrict__ beta,
    h16* __restrict__ oq, h16* __restrict__ ok, h16* __restrict__ ov)
{
    __shared__ float t[64][65];
    int bz = blockIdx.z;
    int b = bz % BB, src = bz / BB;
    const float* x = (src == 0) ? qimg : (src == 1) ? kimg : vimg;
    h16* o = (src == 0) ? oq : (src == 1) ? ok : ov;
    int sx = blockIdx.x * 64, cy = blockIdx.y * 64;
    int tid = threadIdx.x;
    int row = tid >> 4, col4 = (tid & 15) * 4;
    #pragma unroll
    for (int r = 0; r < 64; r += 16) {
        float4 v = *(const float4*)(x + ((long)b*EE + cy + row + r)*SS + sx + col4);
        t[row+r][col4+0] = v.x; t[row+r][col4+1] = v.y;
        t[row+r][col4+2] = v.z; t[row+r][col4+3] = v.w;
    }
    __syncthreads();
    float s0 = 1.f, s1 = 1.f, s2 = 1.f, s3 = 1.f;
    float a0 = 0.f, a1 = 0.f, a2 = 0.f, a3 = 0.f;
    if (src == 0) {
        float acc = 0.f, dummy = 0.f;
        float4 sv = *(const float4*)(sumsq + b*EE + tid*4);
        acc = sqrtf(sv.x) + sqrtf(sv.y) + sqrtf(sv.z) + sqrtf(sv.w);
        blockReduce2(acc, dummy);
        float mg = acc / (float)EE + 1e-6f;
        float4 sq = *(const float4*)(sumsq + b*EE + cy + col4);
        float4 g4 = *(const float4*)(gamma + cy + col4);
        float4 b4 = *(const float4*)(beta + cy + col4);
        s0 = 1.f + (1.f+g4.x)*sqrtf(sq.x)/mg;
        s1 = 1.f + (1.f+g4.y)*sqrtf(sq.y)/mg;
        s2 = 1.f + (1.f+g4.z)*sqrtf(sq.z)/mg;
        s3 = 1.f + (1.f+g4.w)*sqrtf(sq.w)/mg;
        a0 = b4.x; a1 = b4.y; a2 = b4.z; a3 = b4.w;
    }
    #pragma unroll
    for (int r = 0; r < 64; r += 16) {
        int s = row + r;
        float v0 = t[col4+0][s]*s0 + a0;
        float v1 = t[col4+1][s]*s1 + a1;
        float v2 = t[col4+2][s]*s2 + a2;
        float v3 = t[col4+3][s]*s3 + a3;
        long oi = ((long)b*SS + sx + s)*EE + cy + col4;
        *(h162*)(o + oi)     = __floats2half2_rn(v0, v1);
        *(h162*)(o + oi + 2) = __floats2half2_rn(v2, v3);
    }
}

// ---------------- GRN reductions ----------------
__global__ __launch_bounds__(256) void grn_sumsq_cm(const float* __restrict__ x,
                                                    float* __restrict__ sumsq) {
    const float* xr = x + (long)blockIdx.x * SS;
    float acc = 0.f, dummy = 0.f;
    for (int i = threadIdx.x * 4; i < SS; i += 1024) {
        float4 v = *(const float4*)(xr + i);
        acc += v.x*v.x + v.y*v.y + v.z*v.z + v.w*v.w;
    }
    blockReduce2(acc, dummy);
    if (threadIdx.x == 0) sumsq[blockIdx.x] = acc;
}

// GRN2 apply, token-major fp16 in, fp16 out; meangx inline per block
__global__ __launch_bounds__(256) void grn2_apply(const h16* __restrict__ x,
                                                  const float* __restrict__ sumsq,
                                                  const float* __restrict__ gamma,
                                                  const float* __restrict__ beta,
                                                  h16* __restrict__ o) {
    int tid = threadIdx.x;
    long i4 = ((long)blockIdx.x * 256 + tid) * 4;
    int c0 = (int)(i4 & 1023);
    int b = (int)(i4 >> 22);
    float acc = 0.f, dummy = 0.f;
    float4 sv = *(const float4*)(sumsq + b*EE + tid*4);
    acc = sqrtf(sv.x) + sqrtf(sv.y) + sqrtf(sv.z) + sqrtf(sv.w);
    blockReduce2(acc, dummy);
    float mg = acc / (float)EE + 1e-6f;

    float4 g4 = *(const float4*)(gamma + c0);
    float4 b4 = *(const float4*)(beta + c0);
    float4 s4 = *(const float4*)(sumsq + b*EE + c0);
    h162 xa = *(const h162*)(x + i4), xb = *(const h162*)(x + i4 + 2);
    float v0 = __half2float(xa.x), v1 = __half2float(xa.y);
    float v2 = __half2float(xb.x), v3 = __half2float(xb.y);
    float o0 = (1.f+g4.x) * v0 * (sqrtf(s4.x)/mg) + b4.x + v0;
    float o1 = (1.f+g4.y) * v1 * (sqrtf(s4.y)/mg) + b4.y + v1;
    float o2 = (1.f+g4.z) * v2 * (sqrtf(s4.z)/mg) + b4.z + v2;
    float o3 = (1.f+g4.w) * v3 * (sqrtf(s4.w)/mg) + b4.w + v3;
    *(h162*)(o + i4)     = __floats2half2_rn(o0, o1);
    *(h162*)(o + i4 + 2) = __floats2half2_rn(o2, o3);
}

// ---------------- LN stats (mean, rstd) for q and k ----------------
__global__ __launch_bounds__(256) void ln_stats(const h16* __restrict__ q,
                                                const h16* __restrict__ k,
                                                float* __restrict__ st) {
    int row = blockIdx.x;
    const h16* xp = (row < BNS) ? q + (long)row * EE : k + (long)(row - BNS) * EE;
    const h162* xr = (const h162*)xp;
    int tid = threadIdx.x;
    h162 p0 = xr[tid*2], p1 = xr[tid*2 + 1];
    float v0 = __half2float(p0.x), v1 = __half2float(p0.y);
    float v2 = __half2float(p1.x), v3 = __half2float(p1.y);
    float s  = v0 + v1 + v2 + v3;
    float sq = v0*v0 + v1*v1 + v2*v2 + v3*v3;
    blockReduce2(s, sq);
    if (tid == 0) {
        float mean = s / (float)EE;
        float var = sq / (float)EE - mean*mean;
        float rstd = rsqrtf(var + 1e-5f);
        if (row < BNS) { st[row] = mean;       st[BNS + row] = rstd; }
        else           { st[BNS + row] = mean; st[3*BNS + (row - BNS)] = rstd; }
    }
}

// ---------------- linear attention (LN+elu applied inline) ----------------
__global__ __launch_bounds__(256) void kvsum_kernel(const h16* __restrict__ k,
                                                    const h16* __restrict__ v,
                                                    const float* __restrict__ st,
                                                    const float* __restrict__ lnw,
                                                    const float* __restrict__ lnb,
                                                    float* __restrict__ kv,
                                                    float* __restrict__ ksum) {
    int bh = blockIdx.x;
    int b = bh >> 4, h = bh & 15;
    int tid = threadIdx.x;
    __shared__ float ks[16][68], vs[16][68];
    int d0 = (tid >> 4) * 4, e0 = (tid & 15) * 4;
    float acc[4][4] = {};
    float accks[4] = {};
    long tok0 = (long)b * SS + (long)blockIdx.y * 256;
    long base = tok0 * EE + h * DD;
    int ltok = tid >> 4, lc = (tid & 15) * 4;
    float4 wv = *(const float4*)(lnw + h*DD + lc);
    float4 bv = *(const float4*)(lnb + h*DD + lc);
    const float* kmean = st + 2*BNS;
    const float* krstd = st + 3*BNS;
    for (int t0 = 0; t0 < 256; t0 += 16) {
        long gi = base + (long)(t0+ltok)*EE + lc;
        long gtok = tok0 + t0 + ltok;
        float mean = kmean[gtok], rstd = krstd[gtok];
        h162 ka = *(const h162*)(k + gi), kb2 = *(const h162*)(k + gi + 2);
        h162 va = *(const h162*)(v + gi), vb2 = *(const h162*)(v + gi + 2);
        ks[ltok][lc+0] = elu1((__half2float(ka.x)-mean)*rstd*wv.x + bv.x);
        ks[ltok][lc+1] = elu1((__half2float(ka.y)-mean)*rstd*wv.y + bv.y);
        ks[ltok][lc+2] = elu1((__half2float(kb2.x)-mean)*rstd*wv.z + bv.z);
        ks[ltok][lc+3] = elu1((__half2float(kb2.y)-mean)*rstd*wv.w + bv.w);
        vs[ltok][lc+0] = __half2float(va.x); vs[ltok][lc+1] = __half2float(va.y);
        vs[ltok][lc+2] = __half2float(vb2.x); vs[ltok][lc+3] = __half2float(vb2.y);
        __syncthreads();
        #pragma unroll
        for (int t = 0; t < 16; t++) {
            float a[4], bb[4];
            #pragma unroll
            for (int i = 0; i < 4; i++) a[i] = ks[t][d0+i];
            #pragma unroll
            for (int j = 0; j < 4; j++) bb[j] = vs[t][e0+j];
            #pragma unroll
            for (int i = 0; i < 4; i++)
                #pragma unroll
                for (int j = 0; j < 4; j++) acc[i][j] += a[i]*bb[j];
            if (e0 == 0) {
                #pragma unroll
                for (int i = 0; i < 4; i++) accks[i] += a[i];
            }
        }
        __syncthreads();
    }
    long kvbase = (long)bh * DD * DD;
    #pragma unroll
    for (int i = 0; i < 4; i++)
        #pragma unroll
        for (int j = 0; j < 4; j++)
            atomicAdd(&kv[kvbase + (d0+i)*DD + e0+j], acc[i][j]);
    if (e0 == 0)
        #pragma unroll
        for (int i = 0; i < 4; i++) atomicAdd(&ksum[bh*DD + d0+i], accks[i]);
}

// attn = (LNq @ kv) / (LNq . ksum + 1e-8), LN+elu inline on q
__global__ __launch_bounds__(256) void attn_apply_kernel(const h16* __restrict__ q,
                                                         const float* __restrict__ st,
                                                         const float* __restrict__ lnw,
                                                         const float* __restrict__ lnb,
                                                         const float* __restrict__ kv,
                                                         const float* __restrict__ ksum,
                                                         h16* __restrict__ o) {
    int bh = blockIdx.x, sblk = blockIdx.y;
    int b = bh >> 4, h = bh & 15;
    int tid = threadIdx.x;
    __shared__ float qs[64][68];
    __shared__ float kvs[64][64];
    __shared__ float kss[64];
    long kvbase = (long)bh * DD * DD;
    #pragma unroll
    for (int r = 0; r < 4; r++) {
        int idx = (r*256 + tid) * 4;
        *(float4*)&kvs[idx >> 6][idx & 63] = *(const float4*)(kv + kvbase + idx);
    }
    if (tid < 64) kss[tid] = ksum[bh*DD + tid];
    long tok0 = (long)b * SS + (long)sblk * 64;
    long qbase = tok0 * EE + h * DD;
    int ltok = tid >> 4, lc = (tid & 15) * 4;
    float4 wv = *(const float4*)(lnw + h*DD + lc);
    float4 bv = *(const float4*)(lnb + h*DD + lc);
    const float* qmean = st;
    const float* qrstd = st + BNS;
    #pragma unroll
    for (int r = 0; r < 4; r++) {
        long gi = qbase + (long)(ltok + r*16)*EE + lc;
        long gtok = tok0 + ltok + r*16;
        float mean = qmean[gtok], rstd = qrstd[gtok];
        h162 qa = *(const h162*)(q + gi), qb2 = *(const h162*)(q + gi + 2);
        qs[ltok + r*16][lc+0] = elu1((__half2float(qa.x)-mean)*rstd*wv.x + bv.x);
        qs[ltok + r*16][lc+1] = elu1((__half2float(qa.y)-mean)*rstd*wv.y + bv.y);
        qs[ltok + r*16][lc+2] = elu1((__half2float(qb2.x)-mean)*rstd*wv.z + bv.z);
        qs[ltok + r*16][lc+3] = elu1((__half2float(qb2.y)-mean)*rstd*wv.w + bv.w);
    }
    __syncthreads();
    int tok = tid >> 2, e0 = (tid & 3) * 16;
    float num[16] = {};
    float den = 0.f;
    #pragma unroll 8
    for (int d = 0; d < 64; d++) {
        float qd = qs[tok][d];
        den += qd * kss[d];
        #pragma unroll
        for (int j = 0; j < 16; j++) num[j] += qd * kvs[d][e0+j];
    }
    float r = 1.f / (den + 1e-8f);
    long obase = (tok0 + tok) * EE + h * DD + e0;
    #pragma unroll
    for (int j = 0; j < 16; j += 2)
        *(h162*)(o + obase + j) = __floats2half2_rn(num[j] * r, num[j+1] * r);
}

// ---------------- residual / transpose kernels (64x64 tiles) ----------------
__global__ __launch_bounds__(256) void make_working(const float* __restrict__ qimg,
                             const h16* __restrict__ attn_out,
                             const float* __restrict__ ascal,
                             h16* __restrict__ work,
                             float* __restrict__ sumsq) {
    __shared__ float t[64][65];
    __shared__ float ssq[64];
    int sx = blockIdx.x * 64, cy = blockIdx.y * 64, b = blockIdx.z;
    int tid = threadIdx.x;
    int row = tid >> 4, col4 = (tid & 15) * 4;
    #pragma unroll
    for (int r = 0; r < 64; r += 16) {
        float4 v = *(const float4*)(qimg + ((long)b*EE + cy + row + r)*SS + sx + col4);
        t[row+r][col4+0] = v.x; t[row+r][col4+1] = v.y;
        t[row+r][col4+2] = v.z; t[row+r][col4+3] = v.w;
    }
    if (tid < 64) ssq[tid] = 0.f;
    __syncthreads();
    float4 asc = *(const float4*)(ascal + cy + col4);
    float a0 = 0.f, a1 = 0.f, a2 = 0.f, a3 = 0.f;
    #pragma unroll
    for (int r = 0; r < 64; r += 16) {
        int s = row + r;
        long o = ((long)b*SS + sx + s)*EE + cy + col4;
        h162 at0 = *(const h162*)(attn_out + o);
        h162 at1 = *(const h162*)(attn_out + o + 2);
        float w0 = t[col4+0][s] + __half2float(at0.x) * asc.x;
        float w1 = t[col4+1][s] + __half2float(at0.y) * asc.y;
        float w2 = t[col4+2][s] + __half2float(at1.x) * asc.z;
        float w3 = t[col4+3][s] + __half2float(at1.y) * asc.w;
        *(h162*)(work + o)     = __floats2half2_rn(w0, w1);
        *(h162*)(work + o + 2) = __floats2half2_rn(w2, w3);
        a0 += w0*w0; a1 += w1*w1; a2 += w2*w2; a3 += w3*w3;
    }
    atomicAdd(&ssq[col4+0], a0);
    atomicAdd(&ssq[col4+1], a1);
    atomicAdd(&ssq[col4+2], a2);
    atomicAdd(&ssq[col4+3], a3);
    __syncthreads();
    if (tid < 64) atomicAdd(&sumsq[b*EE + cy + tid], ssq[tid]);
}

__global__ __launch_bounds__(256) void final_kernel(const float* __restrict__ qimg,
                             const h16* __restrict__ work,
                             const h16* __restrict__ ffn,
                             const float* __restrict__ fscal,
                             const float* __restrict__ finscal,
                             float* __restrict__ out) {
    __shared__ float t[64][65];
    int sx = blockIdx.x * 64, cy = blockIdx.y * 64, b = blockIdx.z;
    int tid = threadIdx.x;
    int row = tid >> 4, col4 = (tid & 15) * 4;
    float4 fs = *(const float4*)(fscal + cy + col4);
    float4 fin = *(const float4*)(finscal + cy + col4);
    #pragma unroll
    for (int r = 0; r < 64; r += 16) {
        int s = row + r;
        long o = ((long)b*SS + sx + s)*EE + cy + col4;
        h162 w0 = *(const h162*)(work + o), w1 = *(const h162*)(work + o + 2);
        h162 f0 = *(const h162*)(ffn + o),  f1 = *(const h162*)(ffn + o + 2);
        t[s][col4+0] = (__half2float(w0.x) + __half2float(f0.x)*fs.x)*fin.x;
        t[s][col4+1] = (__half2float(w0.y) + __half2float(f0.y)*fs.y)*fin.y;
        t[s][col4+2] = (__half2float(w1.x) + __half2float(f1.x)*fs.z)*fin.z;
        t[s][col4+3] = (__half2float(w1.y) + __half2float(f1.y)*fs.w)*fin.w;
    }
    __syncthreads();
    #pragma unroll
    for (int r = 0; r < 64; r += 16) {
        int c = row + r;
        long o = ((long)b*EE + cy + c)*SS + sx + col4;
        float4 qv = *(const float4*)(qimg + o);
        float4 ov;
        ov.x = qv.x + t[col4+0][c];
        ov.y = qv.y + t[col4+1][c];
        ov.z = qv.z + t[col4+2][c];
        ov.w = qv.w + t[col4+3][c];
        *(float4*)(out + o) = ov;
    }
}

// ---------------- host launcher ----------------
extern "C" void kernel_launch(void* const* d_in, const int* in_sizes, int n_in,
                              void* d_out, int out_size) {
    const float* qimg   = (const float*)d_in[0];
    const float* kimg   = (const float*)d_in[1];
    const float* vimg   = (const float*)d_in[2];
    const float* grn1_g = (const float*)d_in[3];
    const float* grn1_b = (const float*)d_in[4];
    const float* q_w    = (const float*)d_in[5];
    const float* q_b    = (const float*)d_in[6];
    const float* k_w    = (const float*)d_in[7];
    const float* k_b    = (const float*)d_in[8];
    const float* v_w    = (const float*)d_in[9];
    const float* v_b    = (const float*)d_in[10];
    const float* o_w    = (const float*)d_in[11];
    const float* o_b    = (const float*)d_in[12];
    const float* lnq_w  = (const float*)d_in[13];
    const float* lnq_b  = (const float*)d_in[14];
    const float* lnk_w  = (const float*)d_in[15];
    const float* lnk_b  = (const float*)d_in[16];
    const float* ascal  = (const float*)d_in[17];
    const float* grn2_g = (const float*)d_in[18];
    const float* grn2_b = (const float*)d_in[19];
    const float* w1     = (const float*)d_in[20];
    const float* b1     = (const float*)d_in[21];
    const float* w2     = (const float*)d_in[22];
    const float* b2     = (const float*)d_in[23];
    const float* fscal  = (const float*)d_in[24];
    const float* finscal= (const float*)d_in[25];

    float *kv, *sumsq, *lnst;
    h16 *work, *xh, *wh, *hh, *o1, *o2;
    cudaGetSymbolAddress((void**)&work, g_work);
    cudaGetSymbolAddress((void**)&xh,   g_x);
    cudaGetSymbolAddress((void**)&wh,   g_w);
    cudaGetSymbolAddress((void**)&hh,   g_h);
    cudaGetSymbolAddress((void**)&o1,   g_o1);
    cudaGetSymbolAddress((void**)&o2,   g_o2);
    cudaGetSymbolAddress((void**)&kv,   g_kv);
    cudaGetSymbolAddress((void**)&sumsq,g_sumsq);
    cudaGetSymbolAddress((void**)&lnst, g_lnst);
    float* ksum = kv + BB*HH*DD*DD;

    h16* qh = hh;
    h16* kh = hh + (long)BNS*EE;
    h16* vh = hh + 2L*BNS*EE;
    h16 *w_q = wh, *w_o = wh + 3*M1;
    h16 *w_1 = wh + 4*M1, *w_2 = wh + 8*M1;

    cudaFuncSetAttribute(gemm_hmma<1>, cudaFuncAttributeMaxDynamicSharedMemorySize, GSMEM);
    cudaFuncSetAttribute(gemm_hmma<2>, cudaFuncAttributeMaxDynamicSharedMemorySize, GSMEM);

    const long ES = (long)EE * SS;
    dim3 tgrid(SS/64, EE/64, BB);

    // All weight conversions in one launch
    cvt_weights<<<1184, 256>>>(q_w, k_w, v_w, o_w, w1, w2, wh);

    // GRN1 sum-of-squares on query image
    grn_sumsq_cm<<<BB*EE, 256>>>(qimg, sumsq);

    // Batched transposes: qimg(+GRN1, meangx inline)->xh, kimg->o1, vimg->o2
    trans3<<<dim3(SS/64, EE/64, BB*3), 256>>>(qimg, kimg, vimg,
        sumsq, grn1_g, grn1_b, xh, o1, o2);

    // Batched Q/K/V projections (grid.z = 3)
    gemm_hmma<2><<<dim3(EE/64, BNS/128, 3), 256, GSMEM>>>(
        xh, o1, o2, w_q, M1, q_b, k_b, v_b, qh, (long)BNS*EE, BNS, EE, EE);

    // LN stats for q and k
    ln_stats<<<2*BNS, 256>>>(qh, kh, lnst);

    // linear attention (LN+elu fused into loads)
    cudaMemsetAsync(kv, 0, (BB*HH*DD*DD + BB*HH*DD) * sizeof(float));
    kvsum_kernel<<<dim3(BB*HH, 16), 256>>>(kh, vh, lnst, lnk_w, lnk_b, kv, ksum);
    attn_apply_kernel<<<dim3(BB*HH, SS/64), 256>>>(qh, lnst, lnq_w, lnq_b,
                                                   kv, ksum, xh);

    // O projection -> o1
    gemm_hmma<2><<<dim3(EE/64, BNS/128, 1), 256, GSMEM>>>(
        xh, nullptr, nullptr, w_o, 0, o_b, nullptr, nullptr, o1, 0, BNS, EE, EE);

    // working (fp16) = qimg^T + oproj * ascal (+ fused GRN2 sumsq)
    cudaMemsetAsync(sumsq, 0, BB*EE * sizeof(float));
    make_working<<<tgrid, 256>>>(qimg, o1, ascal, work, sumsq);
    grn2_apply<<<(int)(BB*ES/1024), 256>>>(work, sumsq, grn2_g, grn2_b, xh);

    // FFN1: silu epilogue -> fp16 hidden
    gemm_hmma<1><<<dim3(E4/64, BNS/128, 1), 256, GSMEM>>>(
        xh, nullptr, nullptr, w_1, 0, b1, nullptr, nullptr, hh, 0, BNS, E4, EE);

    // FFN2 -> o2
    gemm_hmma<2><<<dim3(EE/64, BNS/128, 1), 256, GSMEM>>>(
        hh, nullptr, nullptr, w_2, 0, b2, nullptr, nullptr, o2, 0, BNS, EE, E4);

    // final residual (transpose back to channel-major)
    final_kernel<<<tgrid, 256>>>(qimg, work, o2, fscal, finscal, (float*)d_out);
}

// round 17
// speedup vs baseline: 1.1220x; 1.1220x over previous
#include <cuda_runtime.h>
#include <cuda_fp16.h>
#include <math.h>
#include <stdint.h>

// Problem constants
#define BB 2
#define EE 1024
#define HH 16
#define DD 64
#define SS 4096            // 64*64 spatial tokens per batch
#define BNS (BB*SS)        // 8192 total tokens
#define E4 (4*EE)          // 4096 ffn hidden

typedef __half h16;
typedef __half2 h162;

#define M1 (1L<<20)        // 1M elements (EE*EE)

// ---------------- device scratch ----------------
__device__ h16   g_work[(long)BNS*EE];        // fp16 working residual
__device__ h16   g_x   [(long)BNS*EE];        // fp16 staging (q-act / attn out / grn2 out)
__device__ h16   g_w   [12*M1];               // all 6 weights fp16: q|k|v|o|w1|w2
__device__ h16   g_h   [(long)BNS*E4];        // fp16: q|k|v slices, later ffn hidden
__device__ h16   g_o1  [(long)BNS*EE];        // fp16: k-act staging, later o-proj out
__device__ h16   g_o2  [(long)BNS*EE];        // fp16: v-act staging, later ffn2 out
__device__ float g_kv  [BB*HH*DD*DD + BB*HH*DD];  // kv | ksum
__device__ float g_sumsq[BB*EE];
__device__ float g_meangx[BB];

// ================= helpers =================
__device__ __forceinline__ uint32_t smem_u32(const void* p) {
    uint32_t a;
    asm("{ .reg .u64 t; cvta.to.shared.u64 t, %1; cvt.u32.u64 %0, t; }" : "=r"(a) : "l"(p));
    return a;
}
__device__ __forceinline__ void cp16(uint32_t dst, const void* src) {
    asm volatile("cp.async.cg.shared.global [%0], [%1], 16;" :: "r"(dst), "l"(src));
}
__device__ __forceinline__ uint32_t lds32(uint32_t a) {
    uint32_t v;
    asm volatile("ld.shared.u32 %0, [%1];" : "=r"(v) : "r"(a));
    return v;
}
__device__ __forceinline__ void mma16816(float* c, const uint32_t* a, const uint32_t* b) {
    asm volatile(
        "mma.sync.aligned.m16n8k16.row.col.f32.f16.f16.f32 "
        "{%0,%1,%2,%3}, {%4,%5,%6,%7}, {%8,%9}, {%0,%1,%2,%3};"
        : "+f"(c[0]), "+f"(c[1]), "+f"(c[2]), "+f"(c[3])
        : "r"(a[0]), "r"(a[1]), "r"(a[2]), "r"(a[3]), "r"(b[0]), "r"(b[1]));
}

// ================= GEMM: C[M,N] = A W^T + bias (fp16) =====
// CTA tile 128x64, KT=64, 4 warps (2 M x 2 N), warp tile 64x32.
// 2-stage cp.async; 3 CTAs/SM. grid.z batches independent GEMMs.
// EPI 1: silu -> fp16. EPI 2: fp16 out.
#define TPITCH 144
#define TBYTES_A (128*TPITCH)        // 18432
#define TBYTES_B (64*TPITCH)         // 9216
#define STAGEB (TBYTES_A + TBYTES_B) // 27648
#define GSMEM  (2*STAGEB)            // 55296

template<int EPI>
__global__ __launch_bounds__(128, 3) void gemm_hmma(
    const h16* __restrict__ A0, const h16* __restrict__ A1,
    const h16* __restrict__ A2,
    const h16* __restrict__ Wb, long wStride,
    const float* __restrict__ b0, const float* __restrict__ b1,
    const float* __restrict__ b2,
    h16* __restrict__ CHb, long cStride,
    int M, int N, int K)
{
    extern __shared__ char sm[];
    const uint32_t sbase = smem_u32(sm);
    const int tid = threadIdx.x;
    const int lane = tid & 31, wid = tid >> 5;
    const int warp_m = wid >> 1, warp_n = wid & 1;
    const int m0 = blockIdx.y * 128, n0 = blockIdx.x * 64;
    const int z = blockIdx.z;
    const int lrow = lane >> 2, lpair = lane & 3;

    const h16* A = (z == 0) ? A0 : (z == 1) ? A1 : A2;
    const float* bias = (z == 0) ? b0 : (z == 1) ? b1 : b2;
    const h16* W = Wb + (long)z * wStride;
    h16* CH = CHb + (long)z * cStride;

    float acc[4][4][4];
    #pragma unroll
    for (int i = 0; i < 4; i++)
        #pragma unroll
        for (int j = 0; j < 4; j++)
            #pragma unroll
            for (int t = 0; t < 4; t++) acc[i][j][t] = 0.f;

    const int nk = K >> 6;

    auto load_stage = [&](int buf, int kc) {
        const long kq = (long)kc * 64;
        uint32_t sb = sbase + buf * STAGEB;
        #pragma unroll
        for (int i = 0; i < 12; i++) {
            int p = tid + i * 128;
            int row = p >> 3, ch = p & 7;
            uint32_t d = sb + row * TPITCH + ch * 16;
            if (row < 128) cp16(d, A + (long)(m0 + row) * K + kq + ch * 8);
            else           cp16(d, W + (long)(n0 + row - 128) * K + kq + ch * 8);
        }
        asm volatile("cp.async.commit_group;");
    };

    load_stage(0, 0);
    if (nk > 1) load_stage(1, 1);

    for (int kc = 0; kc < nk; kc++) {
        const int buf = kc & 1;
        if (kc + 1 < nk) asm volatile("cp.async.wait_group 1;");
        else             asm volatile("cp.async.wait_group 0;");
        __syncthreads();

        const uint32_t aB = sbase + buf * STAGEB;
        const uint32_t bB = aB + TBYTES_A;

        #pragma unroll
        for (int s = 0; s < 4; s++) {
            const uint32_t koff = (s * 8 + lpair) * 4;
            uint32_t aF[4][4], bF[4][2];
            #pragma unroll
            for (int mt = 0; mt < 4; mt++) {
                uint32_t r = (warp_m * 64 + mt * 16 + lrow) * TPITCH;
                aF[mt][0] = lds32(aB + r + koff);
                aF[mt][1] = lds32(aB + r + 8*TPITCH + koff);
                aF[mt][2] = lds32(aB + r + koff + 16);
                aF[mt][3] = lds32(aB + r + 8*TPITCH + koff + 16);
            }
            #pragma unroll
            for (int nt = 0; nt < 4; nt++) {
                uint32_t r = (warp_n * 32 + nt * 8 + lrow) * TPITCH;
                bF[nt][0] = lds32(bB + r + koff);
                bF[nt][1] = lds32(bB + r + koff + 16);
            }
            #pragma unroll
            for (int mt = 0; mt < 4; mt++)
                #pragma unroll
                for (int nt = 0; nt < 4; nt++)
                    mma16816(acc[mt][nt], aF[mt], bF[nt]);
        }
        __syncthreads();
        if (kc + 2 < nk) load_stage(buf, kc + 2);
    }

    // ---- epilogue ----
    #pragma unroll
    for (int mt = 0; mt < 4; mt++) {
        #pragma unroll
        for (int nt = 0; nt < 4; nt++) {
            long row = m0 + warp_m * 64 + mt * 16 + lrow;
            int col = n0 + warp_n * 32 + nt * 8 + lpair * 2;
            float b0v = bias[col], b1v = bias[col + 1];
            #pragma unroll
            for (int half = 0; half < 2; half++) {
                long r = row + half * 8;
                float v0 = acc[mt][nt][half*2 + 0] + b0v;
                float v1 = acc[mt][nt][half*2 + 1] + b1v;
                if (EPI == 1) {
                    v0 = v0 / (1.f + expf(-v0));
                    v1 = v1 / (1.f + expf(-v1));
                }
                *(h162*)(CH + r * N + col) = __floats2half2_rn(v0, v1);
            }
        }
    }
}

// ================= converters =================
__global__ __launch_bounds__(256) void cvt_weights(
    const float* __restrict__ qw, const float* __restrict__ kw,
    const float* __restrict__ vw, const float* __restrict__ ow,
    const float* __restrict__ w1, const float* __restrict__ w2,
    h16* __restrict__ out)
{
    const long total = 12 * M1;
    const long stride = (long)gridDim.x * blockDim.x * 4;
    for (long i = ((long)blockIdx.x * blockDim.x + threadIdx.x) * 4; i < total;
         i += stride) {
        const float* src;
        long off;
        if (i < 4*M1) {
            int seg = (int)(i >> 20);
            src = (seg == 0) ? qw : (seg == 1) ? kw : (seg == 2) ? vw : ow;
            off = i & (M1 - 1);
        } else if (i < 8*M1) { src = w1; off = i - 4*M1; }
        else                 { src = w2; off = i - 8*M1; }
        float4 v = *(const float4*)(src + off);
        *(h162*)(out + i)     = __floats2half2_rn(v.x, v.y);
        *(h162*)(out + i + 2) = __floats2half2_rn(v.z, v.w);
    }
}

// batched transpose [B,E,S] fp32 -> [B,S,E] fp16 for 3 sources.
__global__ __launch_bounds__(256) void trans3(
    const float* __restrict__ qimg, const float* __restrict__ kimg,
    const float* __restrict__ vimg,
    const float* __restrict__ sumsq, const float* __restrict__ meangx,
    const float* __restrict__ gamma, const float* __restrict__ beta,
    h16* __restrict__ oq, h16* __restrict__ ok, h16* __restrict__ ov)
{
    __shared__ float t[64][65];
    int bz = blockIdx.z;
    int b = bz % BB, src = bz / BB;
    const float* x = (src == 0) ? qimg : (src == 1) ? kimg : vimg;
    h16* o = (src == 0) ? oq : (src == 1) ? ok : ov;
    int sx = blockIdx.x * 64, cy = blockIdx.y * 64;
    int tid = threadIdx.x;
    int row = tid >> 4, col4 = (tid & 15) * 4;
    #pragma unroll
    for (int r = 0; r < 64; r += 16) {
        float4 v = *(const float4*)(x + ((long)b*EE + cy + row + r)*SS + sx + col4);
        t[row+r][col4+0] = v.x; t[row+r][col4+1] = v.y;
        t[row+r][col4+2] = v.z; t[row+r][col4+3] = v.w;
    }
    __syncthreads();
    float s0 = 1.f, s1 = 1.f, s2 = 1.f, s3 = 1.f;
    float a0 = 0.f, a1 = 0.f, a2 = 0.f, a3 = 0.f;
    if (src == 0) {
        float4 sq = *(const float4*)(sumsq + b*EE + cy + col4);
        float4 g4 = *(const float4*)(gamma + cy + col4);
        float4 b4 = *(const float4*)(beta + cy + col4);
        float mg = meangx[b] + 1e-6f;
        s0 = 1.f + (1.f+g4.x)*sqrtf(sq.x)/mg;
        s1 = 1.f + (1.f+g4.y)*sqrtf(sq.y)/mg;
        s2 = 1.f + (1.f+g4.z)*sqrtf(sq.z)/mg;
        s3 = 1.f + (1.f+g4.w)*sqrtf(sq.w)/mg;
        a0 = b4.x; a1 = b4.y; a2 = b4.z; a3 = b4.w;
    }
    #pragma unroll
    for (int r = 0; r < 64; r += 16) {
        int s = row + r;
        float v0 = t[col4+0][s]*s0 + a0;
        float v1 = t[col4+1][s]*s1 + a1;
        float v2 = t[col4+2][s]*s2 + a2;
        float v3 = t[col4+3][s]*s3 + a3;
        long oi = ((long)b*SS + sx + s)*EE + cy + col4;
        *(h162*)(o + oi)     = __floats2half2_rn(v0, v1);
        *(h162*)(o + oi + 2) = __floats2half2_rn(v2, v3);
    }
}

// ---------------- small helpers ----------------
__inline__ __device__ void blockReduce2(float& a, float& b) {
    #pragma unroll
    for (int off = 16; off > 0; off >>= 1) {
        a += __shfl_down_sync(0xffffffffu, a, off);
        b += __shfl_down_sync(0xffffffffu, b, off);
    }
    __shared__ float sa[8], sb[8];
    int w = threadIdx.x >> 5, l = threadIdx.x & 31;
    if (l == 0) { sa[w] = a; sb[w] = b; }
    __syncthreads();
    if (w == 0) {
        a = (l < 8) ? sa[l] : 0.f;
        b = (l < 8) ? sb[l] : 0.f;
        #pragma unroll
        for (int off = 4; off > 0; off >>= 1) {
            a += __shfl_down_sync(0xffu, a, off);
            b += __shfl_down_sync(0xffu, b, off);
        }
        if (l == 0) { sa[0] = a; sb[0] = b; }
    }
    __syncthreads();
    a = sa[0]; b = sb[0];
}

// ---------------- GRN reductions ----------------
__global__ __launch_bounds__(256) void grn_sumsq_cm(const float* __restrict__ x,
                                                    float* __restrict__ sumsq) {
    const float* xr = x + (long)blockIdx.x * SS;
    float acc = 0.f, dummy = 0.f;
    for (int i = threadIdx.x * 4; i < SS; i += 1024) {
        float4 v = *(const float4*)(xr + i);
        acc += v.x*v.x + v.y*v.y + v.z*v.z + v.w*v.w;
    }
    blockReduce2(acc, dummy);
    if (threadIdx.x == 0) sumsq[blockIdx.x] = acc;
}

__global__ __launch_bounds__(256) void grn_mean(const float* __restrict__ sumsq,
                                                float* __restrict__ meangx) {
    int b = blockIdx.x;
    float s = 0.f, dummy = 0.f;
    for (int c = threadIdx.x; c < EE; c += 256) s += sqrtf(sumsq[b*EE + c]);
    blockReduce2(s, dummy);
    if (threadIdx.x == 0) meangx[b] = s / (float)EE;
}

// GRN2 apply, token-major fp16 in, fp16 out
__global__ __launch_bounds__(256) void grn2_apply(const h16* __restrict__ x,
                                                  const float* __restrict__ sumsq,
                                                  const float* __restrict__ meangx,
                                                  const float* __restrict__ gamma,
                                                  const float* __restrict__ beta,
                                                  h16* __restrict__ o) {
    long i4 = ((long)blockIdx.x * 256 + threadIdx.x) * 4;
    int c0 = (int)(i4 & 1023);
    int b = (int)(i4 >> 22);
    float4 g4 = *(const float4*)(gamma + c0);
    float4 b4 = *(const float4*)(beta + c0);
    float4 s4 = *(const float4*)(sumsq + b*EE + c0);
    float mg = meangx[b] + 1e-6f;
    h162 xa = *(const h162*)(x + i4), xb = *(const h162*)(x + i4 + 2);
    float v0 = __half2float(xa.x), v1 = __half2float(xa.y);
    float v2 = __half2float(xb.x), v3 = __half2float(xb.y);
    float o0 = (1.f+g4.x) * v0 * (sqrtf(s4.x)/mg) + b4.x + v0;
    float o1 = (1.f+g4.y) * v1 * (sqrtf(s4.y)/mg) + b4.y + v1;
    float o2 = (1.f+g4.z) * v2 * (sqrtf(s4.z)/mg) + b4.z + v2;
    float o3 = (1.f+g4.w) * v3 * (sqrtf(s4.w)/mg) + b4.w + v3;
    *(h162*)(o + i4)     = __floats2half2_rn(o0, o1);
    *(h162*)(o + i4 + 2) = __floats2half2_rn(o2, o3);
}

// ---------------- LayerNorm + (elu+1), fp16 in/out, q & k in one launch ----
__global__ __launch_bounds__(256) void ln_elu_h2(h16* __restrict__ q,
                                                 h16* __restrict__ k,
                                                 const float* __restrict__ wq,
                                                 const float* __restrict__ bq,
                                                 const float* __restrict__ wk,
                                                 const float* __restrict__ bk) {
    int row = blockIdx.x;
    h16* xp;
    const float *w, *b;
    if (row < BNS) { xp = q + (long)row * EE; w = wq; b = bq; }
    else           { xp = k + (long)(row - BNS) * EE; w = wk; b = bk; }
    h162* xr = (h162*)xp;
    int tid = threadIdx.x;
    h162 p0 = xr[tid*2], p1 = xr[tid*2 + 1];
    float v0 = __half2float(p0.x), v1 = __half2float(p0.y);
    float v2 = __half2float(p1.x), v3 = __half2float(p1.y);
    float s  = v0 + v1 + v2 + v3;
    float sq = v0*v0 + v1*v1 + v2*v2 + v3*v3;
    blockReduce2(s, sq);
    float mean = s / (float)EE;
    float var = sq / (float)EE - mean*mean;
    float rstd = rsqrtf(var + 1e-5f);
    float4 wv = *(const float4*)(w + tid*4);
    float4 bv = *(const float4*)(b + tid*4);
    float y;
    y = (v0-mean)*rstd*wv.x + bv.x; v0 = (y > 0.f) ? y + 1.f : expf(y);
    y = (v1-mean)*rstd*wv.y + bv.y; v1 = (y > 0.f) ? y + 1.f : expf(y);
    y = (v2-mean)*rstd*wv.z + bv.z; v2 = (y > 0.f) ? y + 1.f : expf(y);
    y = (v3-mean)*rstd*wv.w + bv.w; v3 = (y > 0.f) ? y + 1.f : expf(y);
    xr[tid*2]     = __floats2half2_rn(v0, v1);
    xr[tid*2 + 1] = __floats2half2_rn(v2, v3);
}

// ---------------- linear attention (fp16 inputs) ----------------
__global__ __launch_bounds__(256) void kvsum_kernel(const h16* __restrict__ k,
                                                    const h16* __restrict__ v,
                                                    float* __restrict__ kv,
                                                    float* __restrict__ ksum) {
    int bh = blockIdx.x;
    int b = bh >> 4, h = bh & 15;
    int tid = threadIdx.x;
    __shared__ float ks[16][68], vs[16][68];
    int d0 = (tid >> 4) * 4, e0 = (tid & 15) * 4;
    float acc[4][4] = {};
    float accks[4] = {};
    long base = ((long)b * SS + (long)blockIdx.y * 256) * EE + h * DD;
    int ltok = tid >> 4, lc = (tid & 15) * 4;
    for (int t0 = 0; t0 < 256; t0 += 16) {
        long gi = base + (long)(t0+ltok)*EE + lc;
        h162 ka = *(const h162*)(k + gi), kb2 = *(const h162*)(k + gi + 2);
        h162 va = *(const h162*)(v + gi), vb2 = *(const h162*)(v + gi + 2);
        ks[ltok][lc+0] = __half2float(ka.x); ks[ltok][lc+1] = __half2float(ka.y);
        ks[ltok][lc+2] = __half2float(kb2.x); ks[ltok][lc+3] = __half2float(kb2.y);
        vs[ltok][lc+0] = __half2float(va.x); vs[ltok][lc+1] = __half2float(va.y);
        vs[ltok][lc+2] = __half2float(vb2.x); vs[ltok][lc+3] = __half2float(vb2.y);
        __syncthreads();
        #pragma unroll
        for (int t = 0; t < 16; t++) {
            float a[4], bb[4];
            #pragma unroll
            for (int i = 0; i < 4; i++) a[i] = ks[t][d0+i];
            #pragma unroll
            for (int j = 0; j < 4; j++) bb[j] = vs[t][e0+j];
            #pragma unroll
            for (int i = 0; i < 4; i++)
                #pragma unroll
                for (int j = 0; j < 4; j++) acc[i][j] += a[i]*bb[j];
            if (e0 == 0) {
                #pragma unroll
                for (int i = 0; i < 4; i++) accks[i] += a[i];
            }
        }
        __syncthreads();
    }
    long kvbase = (long)bh * DD * DD;
    #pragma unroll
    for (int i = 0; i < 4; i++)
        #pragma unroll
        for (int j = 0; j < 4; j++)
            atomicAdd(&kv[kvbase + (d0+i)*DD + e0+j], acc[i][j]);
    if (e0 == 0)
        #pragma unroll
        for (int i = 0; i < 4; i++) atomicAdd(&ksum[bh*DD + d0+i], accks[i]);
}

// attn = (q @ kv) / (q . ksum + 1e-8), fp16 in, fp16 out
__global__ __launch_bounds__(256) void attn_apply_kernel(const h16* __restrict__ q,
                                                         const float* __restrict__ kv,
                                                         const float* __restrict__ ksum,
                                                         h16* __restrict__ o) {
    int bh = blockIdx.x, sblk = blockIdx.y;
    int b = bh >> 4, h = bh & 15;
    int tid = threadIdx.x;
    __shared__ float qs[64][68];
    __shared__ float kvs[64][64];
    __shared__ float kss[64];
    long kvbase = (long)bh * DD * DD;
    #pragma unroll
    for (int r = 0; r < 4; r++) {
        int idx = (r*256 + tid) * 4;
        *(float4*)&kvs[idx >> 6][idx & 63] = *(const float4*)(kv + kvbase + idx);
    }
    if (tid < 64) kss[tid] = ksum[bh*DD + tid];
    long qbase = ((long)b * SS + (long)sblk * 64) * EE + h * DD;
    int ltok = tid >> 4, lc = (tid & 15) * 4;
    #pragma unroll
    for (int r = 0; r < 4; r++) {
        long gi = qbase + (long)(ltok + r*16)*EE + lc;
        h162 qa = *(const h162*)(q + gi), qb2 = *(const h162*)(q + gi + 2);
        qs[ltok + r*16][lc+0] = __half2float(qa.x);
        qs[ltok + r*16][lc+1] = __half2float(qa.y);
        qs[ltok + r*16][lc+2] = __half2float(qb2.x);
        qs[ltok + r*16][lc+3] = __half2float(qb2.y);
    }
    __syncthreads();
    int tok = tid >> 2, e0 = (tid & 3) * 16;
    float num[16] = {};
    float den = 0.f;
    #pragma unroll 8
    for (int d = 0; d < 64; d++) {
        float qd = qs[tok][d];
        den += qd * kss[d];
        #pragma unroll
        for (int j = 0; j < 16; j++) num[j] += qd * kvs[d][e0+j];
    }
    float r = 1.f / (den + 1e-8f);
    long obase = ((long)b * SS + (long)sblk * 64 + tok) * EE + h * DD + e0;
    #pragma unroll
    for (int j = 0; j < 16; j += 2)
        *(h162*)(o + obase + j) = __floats2half2_rn(num[j] * r, num[j+1] * r);
}

// ---------------- residual / transpose kernels (64x64 tiles) ----------------
__global__ __launch_bounds__(256) void make_working(const float* __restrict__ qimg,
                             const h16* __restrict__ attn_out,
                             const float* __restrict__ ascal,
                             h16* __restrict__ work,
                             float* __restrict__ sumsq) {
    __shared__ float t[64][65];
    __shared__ float ssq[64];
    int sx = blockIdx.x * 64, cy = blockIdx.y * 64, b = blockIdx.z;
    int tid = threadIdx.x;
    int row = tid >> 4, col4 = (tid & 15) * 4;
    #pragma unroll
    for (int r = 0; r < 64; r += 16) {
        float4 v = *(const float4*)(qimg + ((long)b*EE + cy + row + r)*SS + sx + col4);
        t[row+r][col4+0] = v.x; t[row+r][col4+1] = v.y;
        t[row+r][col4+2] = v.z; t[row+r][col4+3] = v.w;
    }
    if (tid < 64) ssq[tid] = 0.f;
    __syncthreads();
    float4 asc = *(const float4*)(ascal + cy + col4);
    float a0 = 0.f, a1 = 0.f, a2 = 0.f, a3 = 0.f;
    #pragma unroll
    for (int r = 0; r < 64; r += 16) {
        int s = row + r;
        long o = ((long)b*SS + sx + s)*EE + cy + col4;
        h162 at0 = *(const h162*)(attn_out + o);
        h162 at1 = *(const h162*)(attn_out + o + 2);
        float w0 = t[col4+0][s] + __half2float(at0.x) * asc.x;
        float w1 = t[col4+1][s] + __half2float(at0.y) * asc.y;
        float w2 = t[col4+2][s] + __half2float(at1.x) * asc.z;
        float w3 = t[col4+3][s] + __half2float(at1.y) * asc.w;
        *(h162*)(work + o)     = __floats2half2_rn(w0, w1);
        *(h162*)(work + o + 2) = __floats2half2_rn(w2, w3);
        a0 += w0*w0; a1 += w1*w1; a2 += w2*w2; a3 += w3*w3;
    }
    atomicAdd(&ssq[col4+0], a0);
    atomicAdd(&ssq[col4+1], a1);
    atomicAdd(&ssq[col4+2], a2);
    atomicAdd(&ssq[col4+3], a3);
    __syncthreads();
    if (tid < 64) atomicAdd(&sumsq[b*EE + cy + tid], ssq[tid]);
}

__global__ __launch_bounds__(256) void final_kernel(const float* __restrict__ qimg,
                             const h16* __restrict__ work,
                             const h16* __restrict__ ffn,
                             const float* __restrict__ fscal,
                             const float* __restrict__ finscal,
                             float* __restrict__ out) {
    __shared__ float t[64][65];
    int sx = blockIdx.x * 64, cy = blockIdx.y * 64, b = blockIdx.z;
    int tid = threadIdx.x;
    int row = tid >> 4, col4 = (tid & 15) * 4;
    float4 fs = *(const float4*)(fscal + cy + col4);
    float4 fin = *(const float4*)(finscal + cy + col4);
    #pragma unroll
    for (int r = 0; r < 64; r += 16) {
        int s = row + r;
        long o = ((long)b*SS + sx + s)*EE + cy + col4;
        h162 w0 = *(const h162*)(work + o), w1 = *(const h162*)(work + o + 2);
        h162 f0 = *(const h162*)(ffn + o),  f1 = *(const h162*)(ffn + o + 2);
        t[s][col4+0] = (__half2float(w0.x) + __half2float(f0.x)*fs.x)*fin.x;
        t[s][col4+1] = (__half2float(w0.y) + __half2float(f0.y)*fs.y)*fin.y;
        t[s][col4+2] = (__half2float(w1.x) + __half2float(f1.x)*fs.z)*fin.z;
        t[s][col4+3] = (__half2float(w1.y) + __half2float(f1.y)*fs.w)*fin.w;
    }
    __syncthreads();
    #pragma unroll
    for (int r = 0; r < 64; r += 16) {
        int c = row + r;
        long o = ((long)b*EE + cy + c)*SS + sx + col4;
        float4 qv = *(const float4*)(qimg + o);
        float4 ov;
        ov.x = qv.x + t[col4+0][c];
        ov.y = qv.y + t[col4+1][c];
        ov.z = qv.z + t[col4+2][c];
        ov.w = qv.w + t[col4+3][c];
        *(float4*)(out + o) = ov;
    }
}

// ---------------- host launcher ----------------
extern "C" void kernel_launch(void* const* d_in, const int* in_sizes, int n_in,
                              void* d_out, int out_size) {
    const float* qimg   = (const float*)d_in[0];
    const float* kimg   = (const float*)d_in[1];
    const float* vimg   = (const float*)d_in[2];
    const float* grn1_g = (const float*)d_in[3];
    const float* grn1_b = (const float*)d_in[4];
    const float* q_w    = (const float*)d_in[5];
    const float* q_b    = (const float*)d_in[6];
    const float* k_w    = (const float*)d_in[7];
    const float* k_b    = (const float*)d_in[8];
    const float* v_w    = (const float*)d_in[9];
    const float* v_b    = (const float*)d_in[10];
    const float* o_w    = (const float*)d_in[11];
    const float* o_b    = (const float*)d_in[12];
    const float* lnq_w  = (const float*)d_in[13];
    const float* lnq_b  = (const float*)d_in[14];
    const float* lnk_w  = (const float*)d_in[15];
    const float* lnk_b  = (const float*)d_in[16];
    const float* ascal  = (const float*)d_in[17];
    const float* grn2_g = (const float*)d_in[18];
    const float* grn2_b = (const float*)d_in[19];
    const float* w1     = (const float*)d_in[20];
    const float* b1     = (const float*)d_in[21];
    const float* w2     = (const float*)d_in[22];
    const float* b2     = (const float*)d_in[23];
    const float* fscal  = (const float*)d_in[24];
    const float* finscal= (const float*)d_in[25];

    float *kv, *sumsq, *meang;
    h16 *work, *xh, *wh, *hh, *o1, *o2;
    cudaGetSymbolAddress((void**)&work, g_work);
    cudaGetSymbolAddress((void**)&xh,   g_x);
    cudaGetSymbolAddress((void**)&wh,   g_w);
    cudaGetSymbolAddress((void**)&hh,   g_h);
    cudaGetSymbolAddress((void**)&o1,   g_o1);
    cudaGetSymbolAddress((void**)&o2,   g_o2);
    cudaGetSymbolAddress((void**)&kv,   g_kv);
    cudaGetSymbolAddress((void**)&sumsq,g_sumsq);
    cudaGetSymbolAddress((void**)&meang,g_meangx);
    float* ksum = kv + BB*HH*DD*DD;

    h16* qh = hh;
    h16* kh = hh + (long)BNS*EE;
    h16* vh = hh + 2L*BNS*EE;
    h16 *w_q = wh, *w_o = wh + 3*M1;
    h16 *w_1 = wh + 4*M1, *w_2 = wh + 8*M1;

    cudaFuncSetAttribute(gemm_hmma<1>, cudaFuncAttributeMaxDynamicSharedMemorySize, GSMEM);
    cudaFuncSetAttribute(gemm_hmma<2>, cudaFuncAttributeMaxDynamicSharedMemorySize, GSMEM);

    const long ES = (long)EE * SS;
    dim3 tgrid(SS/64, EE/64, BB);

    // All weight conversions in one launch
    cvt_weights<<<1184, 256>>>(q_w, k_w, v_w, o_w, w1, w2, wh);

    // GRN1 reductions on query image
    grn_sumsq_cm<<<BB*EE, 256>>>(qimg, sumsq);
    grn_mean<<<BB, 256>>>(sumsq, meang);

    // Batched transposes: qimg(+GRN1)->xh, kimg->o1, vimg->o2
    trans3<<<dim3(SS/64, EE/64, BB*3), 256>>>(qimg, kimg, vimg,
        sumsq, meang, grn1_g, grn1_b, xh, o1, o2);

    // Batched Q/K/V projections (grid.z = 3)
    gemm_hmma<2><<<dim3(EE/64, BNS/128, 3), 128, GSMEM>>>(
        xh, o1, o2, w_q, M1, q_b, k_b, v_b, qh, (long)BNS*EE, BNS, EE, EE);

    // LayerNorm + elu+1 on q and k
    ln_elu_h2<<<2*BNS, 256>>>(qh, kh, lnq_w, lnq_b, lnk_w, lnk_b);

    // linear attention
    cudaMemsetAsync(kv, 0, (BB*HH*DD*DD + BB*HH*DD) * sizeof(float));
    kvsum_kernel<<<dim3(BB*HH, 16), 256>>>(kh, vh, kv, ksum);
    attn_apply_kernel<<<dim3(BB*HH, SS/64), 256>>>(qh, kv, ksum, xh);

    // O projection -> o1
    gemm_hmma<2><<<dim3(EE/64, BNS/128, 1), 128, GSMEM>>>(
        xh, nullptr, nullptr, w_o, 0, o_b, nullptr, nullptr, o1, 0, BNS, EE, EE);

    // working (fp16) = qimg^T + oproj * ascal (+ fused GRN2 sumsq)
    cudaMemsetAsync(sumsq, 0, BB*EE * sizeof(float));
    make_working<<<tgrid, 256>>>(qimg, o1, ascal, work, sumsq);
    grn_mean<<<BB, 256>>>(sumsq, meang);
    grn2_apply<<<(int)(BB*ES/1024), 256>>>(work, sumsq, meang, grn2_g, grn2_b, xh);

    // FFN1: silu epilogue -> fp16 hidden
    gemm_hmma<1><<<dim3(E4/64, BNS/128, 1), 128, GSMEM>>>(
        xh, nullptr, nullptr, w_1, 0, b1, nullptr, nullptr, hh, 0, BNS, E4, EE);

    // FFN2 -> o2
    gemm_hmma<2><<<dim3(EE/64, BNS/128, 1), 128, GSMEM>>>(
        hh, nullptr, nullptr, w_2, 0, b2, nullptr, nullptr, o2, 0, BNS, EE, E4);

    // final residual (transpose back to channel-major)
    final_kernel<<<tgrid, 256>>>(qimg, work, o2, fscal, finscal, (float*)d_out);
}